// round 11
// baseline (speedup 1.0000x reference)
#include <cuda_runtime.h>
#include <cuda_fp16.h>
#include <cstdint>

#define BB 8
#define TT 4096
#define DM 512

// projected Q, K, V scratch (fp16). Q pre-scaled by (1/sqrt(512))*log2(e).
// V stored TRANSPOSED: g_Vt[b][d][t]. g_Wt: W transposed fp16 [which][n][k].
__device__ __align__(256) __half g_Qh[BB * TT * 64];
__device__ __align__(256) __half g_Kh[BB * TT * 64];
__device__ __align__(256) __half g_Vt[BB * 64 * TT];
__device__ __align__(256) __half g_Wt[3 * 64 * DM];

// ---------------------------------------------------------------------------
// helpers
// ---------------------------------------------------------------------------
__device__ __forceinline__ uint32_t smem_to_u32(const void* p) {
    uint32_t a;
    asm("{ .reg .u64 t; cvta.to.shared.u64 t, %1; cvt.u32.u64 %0, t; }" : "=r"(a) : "l"(p));
    return a;
}
// pack two f32 -> f16x2 (lo = first arg in low half)
__device__ __forceinline__ uint32_t pack_h2(float lo, float hi) {
    uint32_t d; asm("cvt.rn.f16x2.f32 %0, %1, %2;" : "=r"(d) : "f"(hi), "f"(lo)); return d;
}
__device__ __forceinline__ uint32_t hadd2(uint32_t a, uint32_t b) {
    uint32_t d; asm("add.rn.f16x2 %0, %1, %2;" : "=r"(d) : "r"(a), "r"(b)); return d;
}
__device__ __forceinline__ uint32_t h2exp2(uint32_t a) {
    uint32_t d; asm("ex2.approx.f16x2 %0, %1;" : "=r"(d) : "r"(a)); return d;
}
// fp16: D += A(m16 x k16) * B(k16 x n8), f32 accumulate
__device__ __forceinline__ void mma16(float* d, const uint32_t* a, const uint32_t* b) {
    asm volatile(
        "mma.sync.aligned.m16n8k16.row.col.f32.f16.f16.f32 "
        "{%0,%1,%2,%3}, {%4,%5,%6,%7}, {%8,%9}, {%0,%1,%2,%3};"
        : "+f"(d[0]), "+f"(d[1]), "+f"(d[2]), "+f"(d[3])
        : "r"(a[0]), "r"(a[1]), "r"(a[2]), "r"(a[3]), "r"(b[0]), "r"(b[1]));
}
__device__ __forceinline__ void cp16(uint32_t dst, const void* src) {
    asm volatile("cp.async.ca.shared.global [%0], [%1], 16;" :: "r"(dst), "l"(src));
}
__device__ __forceinline__ void cp_commit() { asm volatile("cp.async.commit_group;"); }
template<int N> __device__ __forceinline__ void cp_wait() {
    asm volatile("cp.async.wait_group %0;" :: "n"(N));
}

// ---------------------------------------------------------------------------
// W pre-transpose: g_Wt[which][n][k] = fp16(W[k][n]). Tiny one-off kernel.
// ---------------------------------------------------------------------------
__global__ void wconv_kernel(const float* __restrict__ Wq,
                             const float* __restrict__ Wk,
                             const float* __restrict__ Wv)
{
    int which = blockIdx.x;
    const float* W = (which == 0) ? Wq : ((which == 1) ? Wk : Wv);
    __half* Wt = g_Wt + (size_t)which * 64 * DM;
    for (int i = threadIdx.x; i < DM * 64; i += blockDim.x) {
        int k = i >> 6, n = i & 63;
        Wt[n * DM + k] = __float2half_rn(W[i]);
    }
}

// ---------------------------------------------------------------------------
// Projection: Y[32768,64] = X[32768,512] @ W[512,64], fp16 m16n8k16.
// X staged fp32 (packed to f16x2 at fragment load); W tiles loaded fp16 from
// the pre-transposed g_Wt (B-frags = 2 contiguous u32 LDS, conflict-free).
// fp16 epilogue: which==0 -> g_Qh (scaled), 1 -> g_Kh, 2 -> g_Vt (transposed).
// ---------------------------------------------------------------------------
#define PX_PAD 36
#define PWT_STR 40   // halves; (n*40 + 2*k4)/2 pattern conflict-free
#define P_X0 0
#define P_X1 18432
#define P_W0 36864
#define P_W1 41984
#define P_TOT 47104

__global__ void __launch_bounds__(256, 2) proj_kernel(
    const float* __restrict__ Xq, const float* __restrict__ Xk, const float* __restrict__ Xv)
{
    extern __shared__ char sm[];
    uint32_t smb = smem_to_u32(sm);

    const float* X;
    int which = blockIdx.y;
    if (which == 0)      X = Xq;
    else if (which == 1) X = Xk;
    else                 X = Xv;
    const __half* Wt = g_Wt + (size_t)which * 64 * DM;

    const int tid = threadIdx.x, lane = tid & 31, warp = tid >> 5;
    const int r4 = lane >> 2, k4 = lane & 3;
    const int rowBase = blockIdx.x * 128;

    auto load_chunk = [&](int ch) {
        uint32_t xd = smb + ((ch & 1) ? P_X1 : P_X0);
        uint32_t wd = smb + ((ch & 1) ? P_W1 : P_W0);
        const float* xs = X + (size_t)rowBase * DM + ch * 32;
        #pragma unroll
        for (int i = 0; i < 4; i++) {
            int idx = tid + i * 256;
            int row = idx >> 3, c = idx & 7;
            cp16(xd + row * (PX_PAD * 4) + c * 16, xs + (size_t)row * DM + c * 4);
        }
        {   // W tile: 64 n-rows x 32 k halves (64 B) = 4 segs, one per thread
            int n = tid >> 2, seg = tid & 3;
            cp16(wd + n * (PWT_STR * 2) + seg * 16, Wt + (size_t)n * DM + ch * 32 + seg * 8);
        }
        cp_commit();
    };

    float acc[8][4];
    #pragma unroll
    for (int nb = 0; nb < 8; nb++)
        #pragma unroll
        for (int i = 0; i < 4; i++) acc[nb][i] = 0.0f;

    load_chunk(0);
    for (int ch = 0; ch < 16; ch++) {
        if (ch > 0) __syncthreads();
        if (ch < 15) load_chunk(ch + 1);
        if (ch < 15) cp_wait<1>(); else cp_wait<0>();
        __syncthreads();

        const float*  Xs = (const float*)(sm + ((ch & 1) ? P_X1 : P_X0));
        const __half* Ws = (const __half*)(sm + ((ch & 1) ? P_W1 : P_W0));

        #pragma unroll
        for (int ks = 0; ks < 2; ks++) {
            int c0 = ks * 16 + 2 * k4;
            const float* xp  = Xs + (warp * 16 + r4) * PX_PAD + c0;
            const float* xp8 = xp + 8 * PX_PAD;
            uint32_t a[4] = {
                pack_h2(xp[0],  xp[1]),
                pack_h2(xp8[0], xp8[1]),
                pack_h2(xp[8],  xp[9]),
                pack_h2(xp8[8], xp8[9])
            };
            #pragma unroll
            for (int nb = 0; nb < 8; nb++) {
                const __half* wn = Ws + (nb * 8 + r4) * PWT_STR + c0;
                uint32_t bb[2] = { *(const uint32_t*)(wn), *(const uint32_t*)(wn + 8) };
                mma16(acc[nb], a, bb);
            }
        }
    }

    if (which == 2) {
        // V transposed fp16: g_Vt[(b*64 + d) * TT + t]
        int m = rowBase + warp * 16 + r4;
        int bq = m >> 12;
        int t = m & 4095;
        #pragma unroll
        for (int nb = 0; nb < 8; nb++) {
            int d = nb * 8 + 2 * k4;
            g_Vt[((size_t)bq * 64 + d)     * TT + t]     = __float2half_rn(acc[nb][0]);
            g_Vt[((size_t)bq * 64 + d + 1) * TT + t]     = __float2half_rn(acc[nb][1]);
            g_Vt[((size_t)bq * 64 + d)     * TT + t + 8] = __float2half_rn(acc[nb][2]);
            g_Vt[((size_t)bq * 64 + d + 1) * TT + t + 8] = __float2half_rn(acc[nb][3]);
        }
    } else {
        __half* Yh = (which == 0) ? g_Qh : g_Kh;
        const float sc = (which == 0)
            ? (0.044194173824159216f * 1.4426950408889634f) : 1.0f;
        __half* yp = Yh + (size_t)(rowBase + warp * 16) * 64;
        #pragma unroll
        for (int nb = 0; nb < 8; nb++) {
            int c = nb * 8 + 2 * k4;
            *(uint32_t*)(yp + r4 * 64 + c) =
                pack_h2(acc[nb][0] * sc, acc[nb][1] * sc);
            *(uint32_t*)(yp + (r4 + 8) * 64 + c) =
                pack_h2(acc[nb][2] * sc, acc[nb][3] * sc);
        }
    }
}

// ---------------------------------------------------------------------------
// Flash attention, fp16 m16n8k16. CTA = (128 q-rows, batch); 8 warps x m16;
// Bc=64, 64 tiles; 2 CTAs/SM; single wave.
// Q frags persistent in registers. Softmax fully in f16x2 (pack -> HADD2
// bias -> ex2.approx.f16x2) -> output IS the PV A-fragment. Row-sum l is
// computed BY the tensor core: one extra n-block with B = ones, so l sums
// exactly the fp16 p-hat used in PV (rounding bias cancels in normalize).
// ---------------------------------------------------------------------------
#define AQ_STR 72                      // halves
#define AK_STR 72
#define AV_STR 72
#define A_BIAS 0                       // 4096 halves = 8192 B
#define A_Q    8192                    // 128*144 = 18432 -> 26624
#define A_K0   26624                   // 64*144 = 9216 -> 35840
#define A_K1   35840                   // -> 45056
#define A_V0   45056                   // -> 54272
#define A_V1   54272                   // -> 63488
#define A_TOT  63488

__global__ void __launch_bounds__(256, 2) attn_kernel(
    const int* __restrict__ pad_mask, float* __restrict__ out)
{
    extern __shared__ char sm[];
    uint32_t smb = smem_to_u32(sm);

    const int tid = threadIdx.x, lane = tid & 31, warp = tid >> 5;
    const int b = blockIdx.y, qBase = blockIdx.x * 128;
    const int r4 = lane >> 2, k4 = lane & 3;

    const __half* gK  = g_Kh + (size_t)b * TT * 64;
    const __half* gVt = g_Vt + (size_t)b * 64 * TT;
    const int*    pm  = pad_mask + (size_t)b * TT;

    // stage Q tile (fp16, pre-scaled) — its own commit group
    {
        const __half* src = g_Qh + ((size_t)b * TT + qBase) * 64;
        #pragma unroll
        for (int i = 0; i < 4; i++) {
            int idx = tid + i * 256;
            int row = idx >> 3, c = idx & 7;
            cp16(smb + A_Q + row * (AQ_STR * 2) + c * 16, src + row * 64 + c * 8);
        }
        cp_commit();
    }

    auto load_tile = [&](int t) {
        int base = t * 64;
        uint32_t kd = smb + ((t & 1) ? A_K1 : A_K0);
        uint32_t vd = smb + ((t & 1) ? A_V1 : A_V0);
        #pragma unroll
        for (int i = 0; i < 2; i++) {
            int idx = tid + i * 256;
            int row = idx >> 3, c = idx & 7;
            cp16(kd + row * (AK_STR * 2) + c * 16, gK + (size_t)(base + row) * 64 + c * 8);
        }
        #pragma unroll
        for (int i = 0; i < 2; i++) {
            int idx = tid + i * 256;
            int d = idx >> 3, c = idx & 7;
            cp16(vd + d * (AV_STR * 2) + c * 16, gVt + (size_t)d * TT + base + c * 8);
        }
        cp_commit();
    };

    load_tile(0);

    // mask bias as f16 (finite large-negative; exp2 -> exactly 0)
    {
        uint32_t* b16 = (uint32_t*)(sm + A_BIAS);
        for (int i = tid; i < TT / 2; i += 256) {
            int2 m = *(const int2*)(pm + 2 * i);
            b16[i] = (m.x ? 0x0000FBFFu : 0u) | (m.y ? 0xFBFF0000u : 0u);
        }
    }

    cp_wait<1>();        // Q group done (tile0 may still be pending)
    __syncthreads();

    // persistent Q fragments (fp16, 16 u32)
    uint32_t Qr[4][4];
    {
        const __half* Qs = (const __half*)(sm + A_Q);
        int r0 = warp * 16 + r4;
        #pragma unroll
        for (int ks = 0; ks < 4; ks++) {
            int c0 = ks * 16 + 2 * k4;
            Qr[ks][0] = *(const uint32_t*)(Qs + r0 * AQ_STR + c0);
            Qr[ks][1] = *(const uint32_t*)(Qs + (r0 + 8) * AQ_STR + c0);
            Qr[ks][2] = *(const uint32_t*)(Qs + r0 * AQ_STR + c0 + 8);
            Qr[ks][3] = *(const uint32_t*)(Qs + (r0 + 8) * AQ_STR + c0 + 8);
        }
    }

    float o[8][4];
    float lacc[4] = {0.f, 0.f, 0.f, 0.f};   // row-sum accumulator (via mma)
    #pragma unroll
    for (int nb = 0; nb < 8; nb++)
        #pragma unroll
        for (int i = 0; i < 4; i++) o[nb][i] = 0.0f;

    const uint32_t ONES = 0x3C003C00u;       // f16x2 (1.0, 1.0)
    const uint32_t onesb[2] = { ONES, ONES };
    const int NT = TT / 64;

    for (int t = 0; t < NT; t++) {
        if (t > 0) __syncthreads();           // compute t-1 done -> buffer reuse OK
        if (t < NT - 1) load_tile(t + 1);
        if (t < NT - 1) cp_wait<1>(); else cp_wait<0>();
        __syncthreads();

        const __half* Ks = (const __half*)(sm + ((t & 1) ? A_K1 : A_K0));
        const __half* Vs = (const __half*)(sm + ((t & 1) ? A_V1 : A_V0));
        const uint32_t* bias16 = (const uint32_t*)(sm + A_BIAS) + t * 32;

        // ---- S = Q @ K^T (fp16, 4 ksteps of 16) ----
        float s[8][4];
        #pragma unroll
        for (int nb = 0; nb < 8; nb++) {
            s[nb][0] = 0.0f; s[nb][1] = 0.0f; s[nb][2] = 0.0f; s[nb][3] = 0.0f;
        }
        #pragma unroll
        for (int ks = 0; ks < 4; ks++) {
            int c0 = ks * 16 + 2 * k4;
            #pragma unroll
            for (int nb = 0; nb < 8; nb++) {
                const __half* kk = Ks + (nb * 8 + r4) * AK_STR + c0;
                uint32_t bb[2] = { *(const uint32_t*)(kk), *(const uint32_t*)(kk + 8) };
                mma16(s[nb], Qr[ks], bb);
            }
        }

        // ---- softmax in f16x2: p = exp2(s + bias); result IS the A-frag ----
        uint32_t plo[8], phi[8];
        #pragma unroll
        for (int nb = 0; nb < 8; nb++) {
            uint32_t bv = bias16[nb * 4 + k4];
            plo[nb] = h2exp2(hadd2(pack_h2(s[nb][0], s[nb][1]), bv));
            phi[nb] = h2exp2(hadd2(pack_h2(s[nb][2], s[nb][3]), bv));
        }

        // ---- O += P @ V; l += P @ 1 (extra n-block of ones) ----
        #pragma unroll
        for (int nbS = 0; nbS < 4; nbS++) {
            uint32_t a[4] = { plo[2 * nbS], phi[2 * nbS],
                              plo[2 * nbS + 1], phi[2 * nbS + 1] };
            int sc = nbS * 16 + 2 * k4;
            #pragma unroll
            for (int nb = 0; nb < 8; nb++) {
                const __half* vp = Vs + (nb * 8 + r4) * AV_STR + sc;
                uint32_t bb[2] = { *(const uint32_t*)(vp), *(const uint32_t*)(vp + 8) };
                mma16(o[nb], a, bb);
            }
            mma16(lacc, a, onesb);
        }
    }

    // normalize + store (lacc columns identical; rows r4 / r4+8)
    float i0 = 1.0f / lacc[0], i1 = 1.0f / lacc[2];

    float* op = out + ((size_t)b * TT + qBase + warp * 16) * 64;
    #pragma unroll
    for (int nb = 0; nb < 8; nb++) {
        int c = nb * 8 + 2 * k4;
        *(float2*)(op + r4 * 64 + c)       = make_float2(o[nb][0] * i0, o[nb][1] * i0);
        *(float2*)(op + (r4 + 8) * 64 + c) = make_float2(o[nb][2] * i1, o[nb][3] * i1);
    }
}

// ---------------------------------------------------------------------------
// kernel_launch: inputs (metadata order): k, v, q, pad_mask, Wk, Wq, Wv
// ---------------------------------------------------------------------------
extern "C" void kernel_launch(void* const* d_in, const int* in_sizes, int n_in,
                              void* d_out, int out_size)
{
    const float* k        = (const float*)d_in[0];
    const float* v        = (const float*)d_in[1];
    const float* q        = (const float*)d_in[2];
    const int*   pad_mask = (const int*)d_in[3];
    const float* Wk       = (const float*)d_in[4];
    const float* Wq       = (const float*)d_in[5];
    const float* Wv       = (const float*)d_in[6];
    float* out = (float*)d_out;

    wconv_kernel<<<3, 256>>>(Wq, Wk, Wv);

    cudaFuncSetAttribute(proj_kernel, cudaFuncAttributeMaxDynamicSharedMemorySize, P_TOT);
    dim3 pg(BB * TT / 128, 3);
    proj_kernel<<<pg, 256, P_TOT>>>(q, k, v);

    cudaFuncSetAttribute(attn_kernel, cudaFuncAttributeMaxDynamicSharedMemorySize, A_TOT);
    dim3 ag(TT / 128, BB);
    attn_kernel<<<ag, 256, A_TOT>>>(pad_mask, out);
}

// round 12
// speedup vs baseline: 1.2030x; 1.2030x over previous
#include <cuda_runtime.h>
#include <cuda_fp16.h>
#include <cstdint>

#define BB 8
#define TT 4096
#define DM 512

// projected Q, K, V scratch (fp16). Q pre-scaled by (1/sqrt(512))*log2(e).
// V stored TRANSPOSED: g_Vt[b][d][t]. g_Wt: W transposed fp16 [which][n][k].
__device__ __align__(256) __half g_Qh[BB * TT * 64];
__device__ __align__(256) __half g_Kh[BB * TT * 64];
__device__ __align__(256) __half g_Vt[BB * 64 * TT];
__device__ __align__(256) __half g_Wt[3 * 64 * DM];

// ---------------------------------------------------------------------------
// helpers
// ---------------------------------------------------------------------------
__device__ __forceinline__ uint32_t smem_to_u32(const void* p) {
    uint32_t a;
    asm("{ .reg .u64 t; cvta.to.shared.u64 t, %1; cvt.u32.u64 %0, t; }" : "=r"(a) : "l"(p));
    return a;
}
// pack two f32 -> f16x2 (lo = first arg in low half)
__device__ __forceinline__ uint32_t pack_h2(float lo, float hi) {
    uint32_t d; asm("cvt.rn.f16x2.f32 %0, %1, %2;" : "=r"(d) : "f"(hi), "f"(lo)); return d;
}
__device__ __forceinline__ uint32_t hadd2(uint32_t a, uint32_t b) {
    uint32_t d; asm("add.rn.f16x2 %0, %1, %2;" : "=r"(d) : "r"(a), "r"(b)); return d;
}
__device__ __forceinline__ uint32_t h2exp2(uint32_t a) {
    uint32_t d; asm("ex2.approx.f16x2 %0, %1;" : "=r"(d) : "r"(a)); return d;
}
// fp16: D += A(m16 x k16) * B(k16 x n8), f32 accumulate
__device__ __forceinline__ void mma16(float* d, const uint32_t* a, const uint32_t* b) {
    asm volatile(
        "mma.sync.aligned.m16n8k16.row.col.f32.f16.f16.f32 "
        "{%0,%1,%2,%3}, {%4,%5,%6,%7}, {%8,%9}, {%0,%1,%2,%3};"
        : "+f"(d[0]), "+f"(d[1]), "+f"(d[2]), "+f"(d[3])
        : "r"(a[0]), "r"(a[1]), "r"(a[2]), "r"(a[3]), "r"(b[0]), "r"(b[1]));
}
__device__ __forceinline__ void cp16(uint32_t dst, const void* src) {
    asm volatile("cp.async.ca.shared.global [%0], [%1], 16;" :: "r"(dst), "l"(src));
}
__device__ __forceinline__ void cp_commit() { asm volatile("cp.async.commit_group;"); }
template<int N> __device__ __forceinline__ void cp_wait() {
    asm volatile("cp.async.wait_group %0;" :: "n"(N));
}

// ---------------------------------------------------------------------------
// W pre-transpose: g_Wt[which][n][k] = fp16(W[k][n]).
// 24 blocks (3 matrices x 8 k-tiles of 64). SMEM transpose: coalesced fp32
// reads, coalesced fp16 writes along k, padded stride -> conflict-free.
// ---------------------------------------------------------------------------
__global__ void __launch_bounds__(256) wconv_kernel(
    const float* __restrict__ Wq, const float* __restrict__ Wk,
    const float* __restrict__ Wv)
{
    __shared__ float tile[64][65];
    int which = blockIdx.x >> 3;
    int kb    = (blockIdx.x & 7) * 64;
    const float* W = (which == 0) ? Wq : ((which == 1) ? Wk : Wv);
    __half* Wt = g_Wt + (size_t)which * 64 * DM;
    int tid = threadIdx.x;

    // read 64 k-rows x 64 n-cols, coalesced
    #pragma unroll
    for (int i = 0; i < 16; i++) {
        int idx = tid + i * 256;
        int k = idx >> 6, n = idx & 63;
        tile[k][n] = W[(size_t)(kb + k) * 64 + n];
    }
    __syncthreads();

    // write transposed: consecutive tid -> consecutive k (coalesced 128B)
    #pragma unroll
    for (int i = 0; i < 16; i++) {
        int idx = tid + i * 256;
        int n = idx >> 6, k = idx & 63;
        Wt[(size_t)n * DM + kb + k] = __float2half_rn(tile[k][n]);
    }
}

// ---------------------------------------------------------------------------
// Projection: Y[32768,64] = X[32768,512] @ W[512,64], fp16 m16n8k16.
// X staged fp32 (packed to f16x2 at fragment load); W tiles loaded fp16 from
// the pre-transposed g_Wt (B-frags = 2 contiguous u32 LDS, conflict-free).
// fp16 epilogue: which==0 -> g_Qh (scaled), 1 -> g_Kh, 2 -> g_Vt (transposed).
// ---------------------------------------------------------------------------
#define PX_PAD 36
#define PWT_STR 40   // halves; conflict-free B-frag pattern
#define P_X0 0
#define P_X1 18432
#define P_W0 36864
#define P_W1 41984
#define P_TOT 47104

__global__ void __launch_bounds__(256, 2) proj_kernel(
    const float* __restrict__ Xq, const float* __restrict__ Xk, const float* __restrict__ Xv)
{
    extern __shared__ char sm[];
    uint32_t smb = smem_to_u32(sm);

    const float* X;
    int which = blockIdx.y;
    if (which == 0)      X = Xq;
    else if (which == 1) X = Xk;
    else                 X = Xv;
    const __half* Wt = g_Wt + (size_t)which * 64 * DM;

    const int tid = threadIdx.x, lane = tid & 31, warp = tid >> 5;
    const int r4 = lane >> 2, k4 = lane & 3;
    const int rowBase = blockIdx.x * 128;

    auto load_chunk = [&](int ch) {
        uint32_t xd = smb + ((ch & 1) ? P_X1 : P_X0);
        uint32_t wd = smb + ((ch & 1) ? P_W1 : P_W0);
        const float* xs = X + (size_t)rowBase * DM + ch * 32;
        #pragma unroll
        for (int i = 0; i < 4; i++) {
            int idx = tid + i * 256;
            int row = idx >> 3, c = idx & 7;
            cp16(xd + row * (PX_PAD * 4) + c * 16, xs + (size_t)row * DM + c * 4);
        }
        {   // W tile: 64 n-rows x 32 k halves (64 B) = 4 segs, one per thread
            int n = tid >> 2, seg = tid & 3;
            cp16(wd + n * (PWT_STR * 2) + seg * 16, Wt + (size_t)n * DM + ch * 32 + seg * 8);
        }
        cp_commit();
    };

    float acc[8][4];
    #pragma unroll
    for (int nb = 0; nb < 8; nb++)
        #pragma unroll
        for (int i = 0; i < 4; i++) acc[nb][i] = 0.0f;

    load_chunk(0);
    for (int ch = 0; ch < 16; ch++) {
        if (ch > 0) __syncthreads();
        if (ch < 15) load_chunk(ch + 1);
        if (ch < 15) cp_wait<1>(); else cp_wait<0>();
        __syncthreads();

        const float*  Xs = (const float*)(sm + ((ch & 1) ? P_X1 : P_X0));
        const __half* Ws = (const __half*)(sm + ((ch & 1) ? P_W1 : P_W0));

        #pragma unroll
        for (int ks = 0; ks < 2; ks++) {
            int c0 = ks * 16 + 2 * k4;
            const float* xp  = Xs + (warp * 16 + r4) * PX_PAD + c0;
            const float* xp8 = xp + 8 * PX_PAD;
            uint32_t a[4] = {
                pack_h2(xp[0],  xp[1]),
                pack_h2(xp8[0], xp8[1]),
                pack_h2(xp[8],  xp[9]),
                pack_h2(xp8[8], xp8[9])
            };
            #pragma unroll
            for (int nb = 0; nb < 8; nb++) {
                const __half* wn = Ws + (nb * 8 + r4) * PWT_STR + c0;
                uint32_t bb[2] = { *(const uint32_t*)(wn), *(const uint32_t*)(wn + 8) };
                mma16(acc[nb], a, bb);
            }
        }
    }

    if (which == 2) {
        // V transposed fp16: g_Vt[(b*64 + d) * TT + t]
        int m = rowBase + warp * 16 + r4;
        int bq = m >> 12;
        int t = m & 4095;
        #pragma unroll
        for (int nb = 0; nb < 8; nb++) {
            int d = nb * 8 + 2 * k4;
            g_Vt[((size_t)bq * 64 + d)     * TT + t]     = __float2half_rn(acc[nb][0]);
            g_Vt[((size_t)bq * 64 + d + 1) * TT + t]     = __float2half_rn(acc[nb][1]);
            g_Vt[((size_t)bq * 64 + d)     * TT + t + 8] = __float2half_rn(acc[nb][2]);
            g_Vt[((size_t)bq * 64 + d + 1) * TT + t + 8] = __float2half_rn(acc[nb][3]);
        }
    } else {
        __half* Yh = (which == 0) ? g_Qh : g_Kh;
        const float sc = (which == 0)
            ? (0.044194173824159216f * 1.4426950408889634f) : 1.0f;
        __half* yp = Yh + (size_t)(rowBase + warp * 16) * 64;
        #pragma unroll
        for (int nb = 0; nb < 8; nb++) {
            int c = nb * 8 + 2 * k4;
            *(uint32_t*)(yp + r4 * 64 + c) =
                pack_h2(acc[nb][0] * sc, acc[nb][1] * sc);
            *(uint32_t*)(yp + (r4 + 8) * 64 + c) =
                pack_h2(acc[nb][2] * sc, acc[nb][3] * sc);
        }
    }
}

// ---------------------------------------------------------------------------
// Flash attention, fp16 m16n8k16. CTA = (128 q-rows, batch); 8 warps x m16;
// Bc=64, 64 tiles; 2 CTAs/SM; single wave.
// Q frags persistent in registers. Softmax fully in f16x2 (pack -> HADD2
// bias -> ex2.approx.f16x2) -> output IS the PV A-fragment. Row-sum l is
// computed BY the tensor core: one extra n-block with B = ones, so l sums
// exactly the fp16 p-hat used in PV (rounding bias cancels in normalize).
// ---------------------------------------------------------------------------
#define AQ_STR 72                      // halves
#define AK_STR 72
#define AV_STR 72
#define A_BIAS 0                       // 4096 halves = 8192 B
#define A_Q    8192                    // 128*144 = 18432 -> 26624
#define A_K0   26624                   // 64*144 = 9216 -> 35840
#define A_K1   35840                   // -> 45056
#define A_V0   45056                   // -> 54272
#define A_V1   54272                   // -> 63488
#define A_TOT  63488

__global__ void __launch_bounds__(256, 2) attn_kernel(
    const int* __restrict__ pad_mask, float* __restrict__ out)
{
    extern __shared__ char sm[];
    uint32_t smb = smem_to_u32(sm);

    const int tid = threadIdx.x, lane = tid & 31, warp = tid >> 5;
    const int b = blockIdx.y, qBase = blockIdx.x * 128;
    const int r4 = lane >> 2, k4 = lane & 3;

    const __half* gK  = g_Kh + (size_t)b * TT * 64;
    const __half* gVt = g_Vt + (size_t)b * 64 * TT;
    const int*    pm  = pad_mask + (size_t)b * TT;

    // stage Q tile (fp16, pre-scaled) — its own commit group
    {
        const __half* src = g_Qh + ((size_t)b * TT + qBase) * 64;
        #pragma unroll
        for (int i = 0; i < 4; i++) {
            int idx = tid + i * 256;
            int row = idx >> 3, c = idx & 7;
            cp16(smb + A_Q + row * (AQ_STR * 2) + c * 16, src + row * 64 + c * 8);
        }
        cp_commit();
    }

    auto load_tile = [&](int t) {
        int base = t * 64;
        uint32_t kd = smb + ((t & 1) ? A_K1 : A_K0);
        uint32_t vd = smb + ((t & 1) ? A_V1 : A_V0);
        #pragma unroll
        for (int i = 0; i < 2; i++) {
            int idx = tid + i * 256;
            int row = idx >> 3, c = idx & 7;
            cp16(kd + row * (AK_STR * 2) + c * 16, gK + (size_t)(base + row) * 64 + c * 8);
        }
        #pragma unroll
        for (int i = 0; i < 2; i++) {
            int idx = tid + i * 256;
            int d = idx >> 3, c = idx & 7;
            cp16(vd + d * (AV_STR * 2) + c * 16, gVt + (size_t)d * TT + base + c * 8);
        }
        cp_commit();
    };

    load_tile(0);

    // mask bias as f16 (finite large-negative; exp2 -> exactly 0)
    {
        uint32_t* b16 = (uint32_t*)(sm + A_BIAS);
        for (int i = tid; i < TT / 2; i += 256) {
            int2 m = *(const int2*)(pm + 2 * i);
            b16[i] = (m.x ? 0x0000FBFFu : 0u) | (m.y ? 0xFBFF0000u : 0u);
        }
    }

    cp_wait<1>();        // Q group done (tile0 may still be pending)
    __syncthreads();

    // persistent Q fragments (fp16, 16 u32)
    uint32_t Qr[4][4];
    {
        const __half* Qs = (const __half*)(sm + A_Q);
        int r0 = warp * 16 + r4;
        #pragma unroll
        for (int ks = 0; ks < 4; ks++) {
            int c0 = ks * 16 + 2 * k4;
            Qr[ks][0] = *(const uint32_t*)(Qs + r0 * AQ_STR + c0);
            Qr[ks][1] = *(const uint32_t*)(Qs + (r0 + 8) * AQ_STR + c0);
            Qr[ks][2] = *(const uint32_t*)(Qs + r0 * AQ_STR + c0 + 8);
            Qr[ks][3] = *(const uint32_t*)(Qs + (r0 + 8) * AQ_STR + c0 + 8);
        }
    }

    float o[8][4];
    float lacc[4] = {0.f, 0.f, 0.f, 0.f};   // row-sum accumulator (via mma)
    #pragma unroll
    for (int nb = 0; nb < 8; nb++)
        #pragma unroll
        for (int i = 0; i < 4; i++) o[nb][i] = 0.0f;

    const uint32_t ONES = 0x3C003C00u;       // f16x2 (1.0, 1.0)
    const uint32_t onesb[2] = { ONES, ONES };
    const int NT = TT / 64;

    for (int t = 0; t < NT; t++) {
        if (t > 0) __syncthreads();           // compute t-1 done -> buffer reuse OK
        if (t < NT - 1) load_tile(t + 1);
        if (t < NT - 1) cp_wait<1>(); else cp_wait<0>();
        __syncthreads();

        const __half* Ks = (const __half*)(sm + ((t & 1) ? A_K1 : A_K0));
        const __half* Vs = (const __half*)(sm + ((t & 1) ? A_V1 : A_V0));
        const uint32_t* bias16 = (const uint32_t*)(sm + A_BIAS) + t * 32;

        // ---- S = Q @ K^T (fp16, 4 ksteps of 16) ----
        float s[8][4];
        #pragma unroll
        for (int nb = 0; nb < 8; nb++) {
            s[nb][0] = 0.0f; s[nb][1] = 0.0f; s[nb][2] = 0.0f; s[nb][3] = 0.0f;
        }
        #pragma unroll
        for (int ks = 0; ks < 4; ks++) {
            int c0 = ks * 16 + 2 * k4;
            #pragma unroll
            for (int nb = 0; nb < 8; nb++) {
                const __half* kk = Ks + (nb * 8 + r4) * AK_STR + c0;
                uint32_t bb[2] = { *(const uint32_t*)(kk), *(const uint32_t*)(kk + 8) };
                mma16(s[nb], Qr[ks], bb);
            }
        }

        // ---- softmax in f16x2: p = exp2(s + bias); result IS the A-frag ----
        uint32_t plo[8], phi[8];
        #pragma unroll
        for (int nb = 0; nb < 8; nb++) {
            uint32_t bv = bias16[nb * 4 + k4];
            plo[nb] = h2exp2(hadd2(pack_h2(s[nb][0], s[nb][1]), bv));
            phi[nb] = h2exp2(hadd2(pack_h2(s[nb][2], s[nb][3]), bv));
        }

        // ---- O += P @ V; l += P @ 1 (extra n-block of ones) ----
        #pragma unroll
        for (int nbS = 0; nbS < 4; nbS++) {
            uint32_t a[4] = { plo[2 * nbS], phi[2 * nbS],
                              plo[2 * nbS + 1], phi[2 * nbS + 1] };
            int sc = nbS * 16 + 2 * k4;
            #pragma unroll
            for (int nb = 0; nb < 8; nb++) {
                const __half* vp = Vs + (nb * 8 + r4) * AV_STR + sc;
                uint32_t bb[2] = { *(const uint32_t*)(vp), *(const uint32_t*)(vp + 8) };
                mma16(o[nb], a, bb);
            }
            mma16(lacc, a, onesb);
        }
    }

    // normalize + store (lacc columns identical; rows r4 / r4+8)
    float i0 = 1.0f / lacc[0], i1 = 1.0f / lacc[2];

    float* op = out + ((size_t)b * TT + qBase + warp * 16) * 64;
    #pragma unroll
    for (int nb = 0; nb < 8; nb++) {
        int c = nb * 8 + 2 * k4;
        *(float2*)(op + r4 * 64 + c)       = make_float2(o[nb][0] * i0, o[nb][1] * i0);
        *(float2*)(op + (r4 + 8) * 64 + c) = make_float2(o[nb][2] * i1, o[nb][3] * i1);
    }
}

// ---------------------------------------------------------------------------
// kernel_launch: inputs (metadata order): k, v, q, pad_mask, Wk, Wq, Wv
// ---------------------------------------------------------------------------
extern "C" void kernel_launch(void* const* d_in, const int* in_sizes, int n_in,
                              void* d_out, int out_size)
{
    const float* k        = (const float*)d_in[0];
    const float* v        = (const float*)d_in[1];
    const float* q        = (const float*)d_in[2];
    const int*   pad_mask = (const int*)d_in[3];
    const float* Wk       = (const float*)d_in[4];
    const float* Wq       = (const float*)d_in[5];
    const float* Wv       = (const float*)d_in[6];
    float* out = (float*)d_out;

    wconv_kernel<<<24, 256>>>(Wq, Wk, Wv);

    cudaFuncSetAttribute(proj_kernel, cudaFuncAttributeMaxDynamicSharedMemorySize, P_TOT);
    dim3 pg(BB * TT / 128, 3);
    proj_kernel<<<pg, 256, P_TOT>>>(q, k, v);

    cudaFuncSetAttribute(attn_kernel, cudaFuncAttributeMaxDynamicSharedMemorySize, A_TOT);
    dim3 ag(TT / 128, BB);
    attn_kernel<<<ag, 256, A_TOT>>>(pad_mask, out);
}